// round 3
// baseline (speedup 1.0000x reference)
#include <cuda_runtime.h>
#include <cstddef>

#define IN_F   2048
#define OUT_F  4096
#define BATCHN 131072

// Deterministic scratch (no allocations allowed).
__device__ float g_wpart[16 * IN_F];
__device__ float g_wsum[IN_F];
__device__ float g_bsum;

// ---------------------------------------------------------------------------
// Kernel 1: partial column sums of weight [OUT_F, IN_F].
// grid = (8, 16), block = 256. Block (bx, by) sums rows [by*256, by*256+256)
// for columns [bx*256, bx*256+256). Coalesced across threads (consecutive cols).
// ---------------------------------------------------------------------------
__global__ __launch_bounds__(256) void wsum_partial(const float* __restrict__ w) {
    const int col  = blockIdx.x * 256 + threadIdx.x;
    const int part = blockIdx.y;
    const int r0   = part * (OUT_F / 16);
    float a0 = 0.f, a1 = 0.f, a2 = 0.f, a3 = 0.f;
#pragma unroll 8
    for (int r = 0; r < OUT_F / 16; r += 4) {
        a0 += w[(size_t)(r0 + r + 0) * IN_F + col];
        a1 += w[(size_t)(r0 + r + 1) * IN_F + col];
        a2 += w[(size_t)(r0 + r + 2) * IN_F + col];
        a3 += w[(size_t)(r0 + r + 3) * IN_F + col];
    }
    g_wpart[part * IN_F + col] = (a0 + a1) + (a2 + a3);
}

// ---------------------------------------------------------------------------
// Kernel 2: finalize. Blocks 0..7 reduce the 16 partials per column into
// g_wsum. Block 8 tree-reduces bias into g_bsum. Fully deterministic.
// ---------------------------------------------------------------------------
__global__ __launch_bounds__(256) void finalize(const float* __restrict__ bias) {
    if (blockIdx.x < 8) {
        const int col = blockIdx.x * 256 + threadIdx.x;
        float s = 0.f;
#pragma unroll
        for (int p = 0; p < 16; p++) s += g_wpart[p * IN_F + col];
        g_wsum[col] = s;
    } else {
        __shared__ float sh[256];
        float s = 0.f;
        for (int i = threadIdx.x; i < OUT_F; i += 256) s += bias[i];
        sh[threadIdx.x] = s;
        __syncthreads();
        for (int stride = 128; stride > 0; stride >>= 1) {
            if (threadIdx.x < (unsigned)stride) sh[threadIdx.x] += sh[threadIdx.x + stride];
            __syncthreads();
        }
        if (threadIdx.x == 0) g_bsum = sh[0];
    }
}

// ---------------------------------------------------------------------------
// Kernel 3: out[row] = dot(x[row,:], w_sum) + b_sum.
// Warp-per-row. w_sum staged into 8 KB shared once per block; each warp
// processes ROWS_PER_WARP consecutive rows. Per row, each lane issues 16
// independent LDG.128 (MLP=16) and keeps 4 independent FMA chains.
// grid = BATCHN / (8 warps * 16 rows) = 1024 blocks.
// ---------------------------------------------------------------------------
static constexpr int ROWS_PER_WARP = 16;
static constexpr int WARPS_PER_BLK = 8;

__global__ __launch_bounds__(256) void dot_kernel(const float4* __restrict__ x4,
                                                  float* __restrict__ out) {
    __shared__ float4 shw[IN_F / 4];  // 512 float4 = 8 KB

    const int tid = threadIdx.x;
    // Stage w_sum into shared (2 float4 per thread).
    const float4* w4 = reinterpret_cast<const float4*>(g_wsum);
#pragma unroll
    for (int i = tid; i < IN_F / 4; i += 256) shw[i] = w4[i];
    __syncthreads();

    const float bsum = g_bsum;
    const int warp = tid >> 5;
    const int lane = tid & 31;
    const int row_base = (blockIdx.x * WARPS_PER_BLK + warp) * ROWS_PER_WARP;

    for (int r = 0; r < ROWS_PER_WARP; r++) {
        const int row = row_base + r;
        const float4* __restrict__ xr = x4 + (size_t)row * (IN_F / 4);

        float ax = 0.f, ay = 0.f, az = 0.f, aw = 0.f;
#pragma unroll
        for (int i = 0; i < 16; i++) {
            const float4 xv = xr[i * 32 + lane];   // 512 B coalesced per warp step
            const float4 wv = shw[i * 32 + lane];  // conflict-free LDS.128
            ax = fmaf(xv.x, wv.x, ax);
            ay = fmaf(xv.y, wv.y, ay);
            az = fmaf(xv.z, wv.z, az);
            aw = fmaf(xv.w, wv.w, aw);
        }
        float acc = (ax + ay) + (az + aw);
#pragma unroll
        for (int off = 16; off > 0; off >>= 1)
            acc += __shfl_xor_sync(0xffffffffu, acc, off);
        if (lane == 0) out[row] = acc + bsum;
    }
}

// ---------------------------------------------------------------------------
extern "C" void kernel_launch(void* const* d_in, const int* in_sizes, int n_in,
                              void* d_out, int out_size) {
    const float* x      = (const float*)d_in[0];   // [BATCHN, IN_F]
    const float* weight = (const float*)d_in[1];   // [OUT_F, IN_F]
    const float* bias   = (const float*)d_in[2];   // [OUT_F]
    float* out          = (float*)d_out;           // [BATCHN, 1]

    (void)in_sizes; (void)n_in; (void)out_size;

    dim3 g1(IN_F / 256, 16);
    wsum_partial<<<g1, 256>>>(weight);

    finalize<<<9, 256>>>(bias);

    const int grid = BATCHN / (WARPS_PER_BLK * ROWS_PER_WARP);  // 1024
    dot_kernel<<<grid, 256>>>(reinterpret_cast<const float4*>(x), out);
}